// round 1
// baseline (speedup 1.0000x reference)
#include <cuda_runtime.h>
#include <cuda_bf16.h>
#include <cstdint>

#define T_TOK 2048
#define H_DIM 1024
#define F_DIM 1024
#define E_NUM 8
#define K_TOP 2
#define P_NUM (T_TOK * K_TOP)   // 4096 token-expert pairs
#define NCHUNK 32               // routing chunks of 128 pairs

// ---------------- scratch (static device globals; no allocation) ----------
__device__ int   g_hist[NCHUNK * E_NUM];
__device__ int   g_localrank[P_NUM];
__device__ int   g_base[NCHUNK * E_NUM];
__device__ int   g_offsets[E_NUM + 1];
__device__ int   g_row_token[P_NUM];
__device__ float g_row_weight[P_NUM];
__device__ int   g_iperm[P_NUM];
__device__ float g_act[(size_t)P_NUM * F_DIM];   // 16 MB
__device__ float g_y[(size_t)P_NUM * H_DIM];     // 16 MB

// ---------------- helpers -------------------------------------------------
__device__ __forceinline__ uint32_t f2tf32(float x) {
    uint32_t r;
    asm("cvt.rna.tf32.f32 %0, %1;" : "=r"(r) : "f"(x));
    return r;
}

__device__ __forceinline__ void mma_tf32(float* c, const uint32_t* a,
                                         uint32_t b0, uint32_t b1) {
    asm volatile(
        "mma.sync.aligned.m16n8k8.row.col.f32.tf32.tf32.f32 "
        "{%0,%1,%2,%3}, {%4,%5,%6,%7}, {%8,%9}, {%0,%1,%2,%3};\n"
        : "+f"(c[0]), "+f"(c[1]), "+f"(c[2]), "+f"(c[3])
        : "r"(a[0]), "r"(a[1]), "r"(a[2]), "r"(a[3]), "r"(b0), "r"(b1));
}

__device__ __forceinline__ void cp16(void* smem_dst, const void* gsrc) {
    uint32_t s = (uint32_t)__cvta_generic_to_shared(smem_dst);
    asm volatile("cp.async.cg.shared.global [%0], [%1], 16;\n" ::"r"(s), "l"(gsrc));
}
__device__ __forceinline__ void cp_commit() {
    asm volatile("cp.async.commit_group;\n" ::);
}
template <int N>
__device__ __forceinline__ void cp_wait() {
    asm volatile("cp.async.wait_group %0;\n" ::"n"(N));
}

__device__ __forceinline__ float silu(float x) {
    return x * (1.0f / (1.0f + __expf(-x)));
}

// ---------------- routing: deterministic counting sort by expert ----------
__global__ void route_hist(const int* __restrict__ ids) {
    __shared__ int sE[128];
    __shared__ int h[E_NUM];
    int tid = threadIdx.x, b = blockIdx.x;
    if (tid < E_NUM) h[tid] = 0;
    __syncthreads();
    int p = b * 128 + tid;
    int e = ids[p];
    sE[tid] = e;
    __syncthreads();
    int r = 0;
    for (int j = 0; j < tid; j++) r += (sE[j] == e);
    g_localrank[p] = r;
    atomicAdd(&h[e], 1);
    __syncthreads();
    if (tid < E_NUM) g_hist[b * E_NUM + tid] = h[tid];
}

__global__ void route_scan() {
    if (threadIdx.x == 0 && blockIdx.x == 0) {
        int runs[E_NUM];
        for (int e = 0; e < E_NUM; e++) runs[e] = 0;
        for (int b = 0; b < NCHUNK; b++)
            for (int e = 0; e < E_NUM; e++) {
                g_base[b * E_NUM + e] = runs[e];
                runs[e] += g_hist[b * E_NUM + e];
            }
        int off = 0;
        int eoff[E_NUM];
        for (int e = 0; e < E_NUM; e++) { eoff[e] = off; off += runs[e]; }
        for (int e = 0; e < E_NUM; e++) g_offsets[e] = eoff[e];
        g_offsets[E_NUM] = P_NUM;
        for (int b = 0; b < NCHUNK; b++)
            for (int e = 0; e < E_NUM; e++) g_base[b * E_NUM + e] += eoff[e];
    }
}

__global__ void route_assign(const int* __restrict__ ids,
                             const float* __restrict__ tw) {
    int tid = threadIdx.x, b = blockIdx.x;
    int p = b * 128 + tid;
    int e = ids[p];
    int row = g_base[b * E_NUM + e] + g_localrank[p];
    g_row_token[row] = p >> 1;   // p = t*K + k
    g_row_weight[row] = tw[p];
    g_iperm[p] = row;
}

// ---------------- GEMM1: act = silu(X Wg^T) * (X Wu^T), per expert --------
// M-tile 128 (gathered rows), N-tile 64 (64 gate + 64 up B-rows), K-chunk 32.
// smem per buffer: A 128x36, B 128x36 floats; double-buffered (73728 B).
#define G_PAD 36
#define A_SZ (128 * G_PAD)
#define B_SZ (128 * G_PAD)
#define BUF_SZ (A_SZ + B_SZ)

__global__ void gemm1_kernel(const float* __restrict__ x,
                             const float* __restrict__ wgu) {
    extern __shared__ float sm[];
    __shared__ int tokS[128];

    int e = blockIdx.y;
    int mStart = g_offsets[e] + blockIdx.z * 128;
    int mEnd = g_offsets[e + 1];
    if (mStart >= mEnd) return;
    int n0 = blockIdx.x * 64;

    int tid = threadIdx.x;
    if (tid < 128) {
        int r = min(mStart + tid, mEnd - 1);
        tokS[tid] = g_row_token[r];
    }
    __syncthreads();

    int rg = tid >> 3;          // 0..31
    int c = (tid & 7) * 4;      // 0..28

    // chunk loader
    auto load_chunk = [&](int buf, int k0) {
        float* As = sm + buf * BUF_SZ;
        float* Bs = As + A_SZ;
#pragma unroll
        for (int it = 0; it < 4; it++) {
            int r = it * 32 + rg;
            cp16(&As[r * G_PAD + c], x + (size_t)tokS[r] * H_DIM + k0 + c);
        }
#pragma unroll
        for (int it = 0; it < 4; it++) {
            int r = it * 32 + rg;
            int grow = (r < 64) ? (n0 + r) : (F_DIM + n0 + (r - 64));
            cp16(&Bs[r * G_PAD + c],
                 wgu + ((size_t)e * 2 * F_DIM + grow) * H_DIM + k0 + c);
        }
        cp_commit();
    };

    int warp = tid >> 5, lane = tid & 31;
    int warp_m = warp & 3, warp_n = warp >> 2;   // 4 x 2
    int g = lane >> 2, t = lane & 3;

    float accG[2][4][4];
    float accU[2][4][4];
#pragma unroll
    for (int mi = 0; mi < 2; mi++)
#pragma unroll
        for (int j = 0; j < 4; j++)
#pragma unroll
            for (int q = 0; q < 4; q++) { accG[mi][j][q] = 0.f; accU[mi][j][q] = 0.f; }

    load_chunk(0, 0);
    const int KT = H_DIM / 32;
    for (int kt = 0; kt < KT; kt++) {
        if (kt + 1 < KT) { load_chunk((kt + 1) & 1, (kt + 1) * 32); cp_wait<1>(); }
        else             { cp_wait<0>(); }
        __syncthreads();

        float* As = sm + (kt & 1) * BUF_SZ;
        float* Bs = As + A_SZ;
#pragma unroll
        for (int kk = 0; kk < 4; kk++) {
            uint32_t a[2][4];
#pragma unroll
            for (int mi = 0; mi < 2; mi++) {
                int mr = warp_m * 32 + mi * 16;
                a[mi][0] = f2tf32(As[(mr + g) * G_PAD + kk * 8 + t]);
                a[mi][1] = f2tf32(As[(mr + 8 + g) * G_PAD + kk * 8 + t]);
                a[mi][2] = f2tf32(As[(mr + g) * G_PAD + kk * 8 + t + 4]);
                a[mi][3] = f2tf32(As[(mr + 8 + g) * G_PAD + kk * 8 + t + 4]);
            }
#pragma unroll
            for (int j = 0; j < 4; j++) {
                int nr = warp_n * 32 + j * 8 + g;
                uint32_t bg0 = f2tf32(Bs[nr * G_PAD + kk * 8 + t]);
                uint32_t bg1 = f2tf32(Bs[nr * G_PAD + kk * 8 + t + 4]);
                uint32_t bu0 = f2tf32(Bs[(64 + nr) * G_PAD + kk * 8 + t]);
                uint32_t bu1 = f2tf32(Bs[(64 + nr) * G_PAD + kk * 8 + t + 4]);
#pragma unroll
                for (int mi = 0; mi < 2; mi++) {
                    mma_tf32(accG[mi][j], a[mi], bg0, bg1);
                    mma_tf32(accU[mi][j], a[mi], bu0, bu1);
                }
            }
        }
        __syncthreads();
    }

    // epilogue: silu(gate) * up -> g_act
#pragma unroll
    for (int mi = 0; mi < 2; mi++) {
        int r0 = mStart + warp_m * 32 + mi * 16 + g;
        int r1 = r0 + 8;
#pragma unroll
        for (int j = 0; j < 4; j++) {
            int col = n0 + warp_n * 32 + j * 8 + 2 * t;
            if (r0 < mEnd) {
                float2 v;
                v.x = silu(accG[mi][j][0]) * accU[mi][j][0];
                v.y = silu(accG[mi][j][1]) * accU[mi][j][1];
                *(float2*)&g_act[(size_t)r0 * F_DIM + col] = v;
            }
            if (r1 < mEnd) {
                float2 v;
                v.x = silu(accG[mi][j][2]) * accU[mi][j][2];
                v.y = silu(accG[mi][j][3]) * accU[mi][j][3];
                *(float2*)&g_act[(size_t)r1 * F_DIM + col] = v;
            }
        }
    }
}

// ---------------- GEMM2: y = (act Wd^T) * topk_weight, per expert ---------
// M-tile 128, N-tile 128, K-chunk 32. Same smem footprint as gemm1.
__global__ void gemm2_kernel(const float* __restrict__ wd) {
    extern __shared__ float sm[];

    int e = blockIdx.y;
    int mStart = g_offsets[e] + blockIdx.z * 128;
    int mEnd = g_offsets[e + 1];
    if (mStart >= mEnd) return;
    int n0 = blockIdx.x * 128;

    int tid = threadIdx.x;
    int rg = tid >> 3;
    int c = (tid & 7) * 4;

    auto load_chunk = [&](int buf, int k0) {
        float* As = sm + buf * BUF_SZ;
        float* Bs = As + A_SZ;
#pragma unroll
        for (int it = 0; it < 4; it++) {
            int r = it * 32 + rg;
            int gr = min(mStart + r, mEnd - 1);
            cp16(&As[r * G_PAD + c], g_act + (size_t)gr * F_DIM + k0 + c);
        }
#pragma unroll
        for (int it = 0; it < 4; it++) {
            int r = it * 32 + rg;
            cp16(&Bs[r * G_PAD + c],
                 wd + ((size_t)e * H_DIM + n0 + r) * F_DIM + k0 + c);
        }
        cp_commit();
    };

    int warp = tid >> 5, lane = tid & 31;
    int warp_m = warp & 3, warp_n = warp >> 2;   // 4 x 2, warp_n covers 64 cols
    int g = lane >> 2, t = lane & 3;

    float acc[2][8][4];
#pragma unroll
    for (int mi = 0; mi < 2; mi++)
#pragma unroll
        for (int j = 0; j < 8; j++)
#pragma unroll
            for (int q = 0; q < 4; q++) acc[mi][j][q] = 0.f;

    load_chunk(0, 0);
    const int KT = F_DIM / 32;
    for (int kt = 0; kt < KT; kt++) {
        if (kt + 1 < KT) { load_chunk((kt + 1) & 1, (kt + 1) * 32); cp_wait<1>(); }
        else             { cp_wait<0>(); }
        __syncthreads();

        float* As = sm + (kt & 1) * BUF_SZ;
        float* Bs = As + A_SZ;
#pragma unroll
        for (int kk = 0; kk < 4; kk++) {
            uint32_t a[2][4];
#pragma unroll
            for (int mi = 0; mi < 2; mi++) {
                int mr = warp_m * 32 + mi * 16;
                a[mi][0] = f2tf32(As[(mr + g) * G_PAD + kk * 8 + t]);
                a[mi][1] = f2tf32(As[(mr + 8 + g) * G_PAD + kk * 8 + t]);
                a[mi][2] = f2tf32(As[(mr + g) * G_PAD + kk * 8 + t + 4]);
                a[mi][3] = f2tf32(As[(mr + 8 + g) * G_PAD + kk * 8 + t + 4]);
            }
#pragma unroll
            for (int j = 0; j < 8; j++) {
                int nr = warp_n * 64 + j * 8 + g;
                uint32_t b0 = f2tf32(Bs[nr * G_PAD + kk * 8 + t]);
                uint32_t b1 = f2tf32(Bs[nr * G_PAD + kk * 8 + t + 4]);
#pragma unroll
                for (int mi = 0; mi < 2; mi++) mma_tf32(acc[mi][j], a[mi], b0, b1);
            }
        }
        __syncthreads();
    }

    // epilogue: scale by routing weight, write y scratch
#pragma unroll
    for (int mi = 0; mi < 2; mi++) {
        int r0 = mStart + warp_m * 32 + mi * 16 + g;
        int r1 = r0 + 8;
        float w0 = (r0 < mEnd) ? g_row_weight[r0] : 0.f;
        float w1 = (r1 < mEnd) ? g_row_weight[r1] : 0.f;
#pragma unroll
        for (int j = 0; j < 8; j++) {
            int col = n0 + warp_n * 64 + j * 8 + 2 * t;
            if (r0 < mEnd) {
                float2 v; v.x = acc[mi][j][0] * w0; v.y = acc[mi][j][1] * w0;
                *(float2*)&g_y[(size_t)r0 * H_DIM + col] = v;
            }
            if (r1 < mEnd) {
                float2 v; v.x = acc[mi][j][2] * w1; v.y = acc[mi][j][3] * w1;
                *(float2*)&g_y[(size_t)r1 * H_DIM + col] = v;
            }
        }
    }
}

// ---------------- combine: out[t] = y[iperm[2t]] + y[iperm[2t+1]] ---------
__global__ void combine_kernel(float* __restrict__ out) {
    int tk = blockIdx.x;           // token
    int h4 = threadIdx.x;          // float4 index, 256 per token
    int r0 = g_iperm[2 * tk];
    int r1 = g_iperm[2 * tk + 1];
    float4 a = *(const float4*)&g_y[(size_t)r0 * H_DIM + h4 * 4];
    float4 b = *(const float4*)&g_y[(size_t)r1 * H_DIM + h4 * 4];
    float4 s;
    s.x = a.x + b.x; s.y = a.y + b.y; s.z = a.z + b.z; s.w = a.w + b.w;
    *(float4*)&out[(size_t)tk * H_DIM + h4 * 4] = s;
}

// ---------------- launch ---------------------------------------------------
extern "C" void kernel_launch(void* const* d_in, const int* in_sizes, int n_in,
                              void* d_out, int out_size) {
    const float* x   = (const float*)d_in[0];
    const float* tw  = (const float*)d_in[1];
    const int*   ti  = (const int*)d_in[2];
    const float* wgu = (const float*)d_in[3];
    const float* wd  = (const float*)d_in[4];
    float* out = (float*)d_out;

    route_hist<<<NCHUNK, 128>>>(ti);
    route_scan<<<1, 32>>>();
    route_assign<<<NCHUNK, 128>>>(ti, tw);

    const size_t smem = 2 * BUF_SZ * sizeof(float);   // 73728 B
    static bool attr_set = false;
    if (!attr_set) {
        cudaFuncSetAttribute(gemm1_kernel,
                             cudaFuncAttributeMaxDynamicSharedMemorySize, (int)smem);
        cudaFuncSetAttribute(gemm2_kernel,
                             cudaFuncAttributeMaxDynamicSharedMemorySize, (int)smem);
        attr_set = true;
    }

    gemm1_kernel<<<dim3(F_DIM / 64, E_NUM, P_NUM / 128), 256, smem>>>(x, wgu);
    gemm2_kernel<<<dim3(H_DIM / 128, E_NUM, P_NUM / 128), 256, smem>>>(wd);
    combine_kernel<<<T_TOK, 256>>>(out);
}